// round 16
// baseline (speedup 1.0000x reference)
#include <cuda_runtime.h>
#include <cuda_fp16.h>
#include <math.h>
#include <stdint.h>

// Problem constants
#define TT   2048      // tokens
#define HD   2048      // hidden
#define ID   5632      // intermediate
#define NE   8         // experts
#define KC   64        // K-chunk (fp16 elems) = 128B row

// ---------------- device scratch ----------------
__device__ int   g_count[NE];
__device__ int   g_tok[NE * TT];
__device__ float g_wt [NE * TT];

#define WSZ (NE * (size_t)ID * HD)
__device__ __half g_w1[WSZ];
__device__ __half g_w3[WSZ];
__device__ __half g_w2[WSZ];
__device__ __half g_x  [(size_t)TT * HD];
__device__ __half g_act[NE * (size_t)TT * ID];

// ---------------- helpers ----------------
__device__ __forceinline__ uint32_t smem_u32(const void* p) {
    return (uint32_t)__cvta_generic_to_shared(p);
}
#define SWZ(o) ((o) ^ (((o) >> 3) & 0x70))

__device__ __forceinline__ void cp16(uint32_t dst, const void* src, int sz) {
    asm volatile("cp.async.cg.shared.global [%0], [%1], 16, %2;"
                 :: "r"(dst), "l"(src), "r"(sz) : "memory");
}
#define CP_COMMIT() asm volatile("cp.async.commit_group;" ::: "memory")
#define CP_WAIT1()  asm volatile("cp.async.wait_group 1;" ::: "memory")

__device__ __forceinline__ void ldsm4(uint32_t* r, uint32_t addr) {
    asm volatile("ldmatrix.sync.aligned.m8n8.x4.shared.b16 {%0,%1,%2,%3}, [%4];"
                 : "=r"(r[0]), "=r"(r[1]), "=r"(r[2]), "=r"(r[3]) : "r"(addr));
}
__device__ __forceinline__ void mma_f16(float* d, const uint32_t* a, const uint32_t* b) {
    asm volatile("mma.sync.aligned.m16n8k16.row.col.f32.f16.f16.f32 "
                 "{%0,%1,%2,%3}, {%4,%5,%6,%7}, {%8,%9}, {%0,%1,%2,%3};"
                 : "+f"(d[0]), "+f"(d[1]), "+f"(d[2]), "+f"(d[3])
                 : "r"(a[0]), "r"(a[1]), "r"(a[2]), "r"(a[3]),
                   "r"(b[0]), "r"(b[1]));
}

// A-fragment ldmatrix address (m16 x k16 at (mbase, kb*16) within 128B-row tile)
__device__ __forceinline__ uint32_t a_addr(int mbase, int kb, int lane) {
    int row = mbase + ((lane >> 3) & 1) * 8 + (lane & 7);
    uint32_t off = (uint32_t)(row * 128 + kb * 32 + (lane >> 4) * 16);
    return SWZ(off);
}
// B-fragment ldmatrix address (n16 x k16 at (nbase, kb*16))
__device__ __forceinline__ uint32_t b_addr(int nbase, int kb, int lane) {
    int row = nbase + ((lane >> 4) << 3) + (lane & 7);
    uint32_t off = (uint32_t)(row * 128 + kb * 32 + ((lane >> 3) & 1) * 16);
    return SWZ(off);
}

// ---------------- fp32 -> fp16 convert (8 elems/thread) ----------------
__global__ void cvt_kernel(const float* __restrict__ src,
                           __half* __restrict__ dst, int n8) {
    int i = blockIdx.x * blockDim.x + threadIdx.x;
    if (i >= n8) return;
    const float4* s = (const float4*)src + (size_t)i * 2;
    float4 v0 = s[0];
    float4 v1 = s[1];
    __half2 p0 = __floats2half2_rn(v0.x, v0.y);
    __half2 p1 = __floats2half2_rn(v0.z, v0.w);
    __half2 p2 = __floats2half2_rn(v1.x, v1.y);
    __half2 p3 = __floats2half2_rn(v1.z, v1.w);
    uint4 u;
    u.x = *(uint32_t*)&p0; u.y = *(uint32_t*)&p1;
    u.z = *(uint32_t*)&p2; u.w = *(uint32_t*)&p3;
    ((uint4*)dst)[i] = u;
}

// fused w1+w3 convert over a contiguous slice
__global__ void cvt2_kernel(const float* __restrict__ sa,
                            const float* __restrict__ sb,
                            __half* __restrict__ da,
                            __half* __restrict__ db, int n8) {
    int i = blockIdx.x * blockDim.x + threadIdx.x;
    const float* src;
    __half* dst;
    if (i < n8) { src = sa; dst = da; }
    else        { src = sb; dst = db; i -= n8; if (i >= n8) return; }
    const float4* s = (const float4*)src + (size_t)i * 2;
    float4 v0 = s[0];
    float4 v1 = s[1];
    __half2 p0 = __floats2half2_rn(v0.x, v0.y);
    __half2 p1 = __floats2half2_rn(v0.z, v0.w);
    __half2 p2 = __floats2half2_rn(v1.x, v1.y);
    __half2 p3 = __floats2half2_rn(v1.z, v1.w);
    uint4 u;
    u.x = *(uint32_t*)&p0; u.y = *(uint32_t*)&p1;
    u.z = *(uint32_t*)&p2; u.w = *(uint32_t*)&p3;
    ((uint4*)dst)[i] = u;
}

// ---------------- router ----------------
__global__ void route_kernel(const float* __restrict__ x,
                             const float* __restrict__ gw) {
    const int t   = blockIdx.x;
    const int tid = threadIdx.x;   // 128
    float p[NE];
#pragma unroll
    for (int e = 0; e < NE; e++) p[e] = 0.f;
    const float* xr = x + (size_t)t * HD;
    for (int h = tid; h < HD; h += 128) {
        float xv = xr[h];
#pragma unroll
        for (int e = 0; e < NE; e++) p[e] += xv * gw[e * HD + h];
    }
    __shared__ float sh[NE][128];
#pragma unroll
    for (int e = 0; e < NE; e++) sh[e][tid] = p[e];
    __syncthreads();
    for (int off = 64; off > 0; off >>= 1) {
        if (tid < off) {
#pragma unroll
            for (int e = 0; e < NE; e++) sh[e][tid] += sh[e][tid + off];
        }
        __syncthreads();
    }
    if (tid == 0) {
        float l[NE];
#pragma unroll
        for (int e = 0; e < NE; e++) l[e] = sh[e][0];
        int i0 = 0;
#pragma unroll
        for (int e = 1; e < NE; e++) if (l[e] > l[i0]) i0 = e;
        int i1 = (i0 == 0) ? 1 : 0;
#pragma unroll
        for (int e = 0; e < NE; e++) if (e != i0 && l[e] > l[i1]) i1 = e;
        float d  = expf(l[i1] - l[i0]);
        float w0 = 1.f / (1.f + d);
        float w1 = d / (1.f + d);
        int p0 = atomicAdd(&g_count[i0], 1);
        g_tok[i0 * TT + p0] = t;  g_wt[i0 * TT + p0] = w0;
        int p1 = atomicAdd(&g_count[i1], 1);
        g_tok[i1 * TT + p1] = t;  g_wt[i1 * TT + p1] = w1;
    }
}

// SMEM: [0..512) s_tok, [512..1024) s_wt, 3 stages from 1024, 32KB each
#define STAGE_B 32768
#define NSTAGE  3
#define SMEM_SZ (1024 + NSTAGE * STAGE_B)

// ---------------- GEMM1: act = silu(x@w1^T) * (x@w3^T) ----------------
// CTA 128(M) x 64(N); 8 warps 4x2 of 32x32. Grid: (n, m, nz) with n fastest.
__device__ __forceinline__ void g1_load(char* sb, const int* s_tok,
                                        int e, int n0, int k0, int tid) {
    char* xs = sb;
    char* w1 = sb + 16384;
    char* w3 = sb + 24576;
#pragma unroll
    for (int it = 0; it < 4; it++) {
        int i = tid + it * 256;
        int row = i >> 3, c16 = i & 7;
        int tok = s_tok[row];
        uint32_t doff = SWZ((uint32_t)(row * 128 + c16 * 16));
        size_t goff = (size_t)(tok < 0 ? 0 : tok) * HD + k0 + c16 * 8;
        cp16(smem_u32(xs + doff), g_x + goff, (tok < 0) ? 0 : 16);
    }
#pragma unroll
    for (int it = 0; it < 2; it++) {
        int i = tid + it * 256;
        int row = i >> 3, c16 = i & 7;
        uint32_t doff = SWZ((uint32_t)(row * 128 + c16 * 16));
        size_t goff = ((size_t)e * ID + n0 + row) * HD + k0 + c16 * 8;
        cp16(smem_u32(w1 + doff), g_w1 + goff, 16);
        cp16(smem_u32(w3 + doff), g_w3 + goff, 16);
    }
}

__global__ __launch_bounds__(256, 2)
void gemm1_kernel(int ebase) {
    extern __shared__ char smem[];
    const int e   = ebase + blockIdx.z;
    const int cnt = g_count[e];
    const int m0  = blockIdx.y * 128;
    if (m0 >= cnt) return;
    const int n0  = blockIdx.x * 64;
    const int tid  = threadIdx.x;
    const int wid  = tid >> 5, lane = tid & 31;

    int* s_tok = (int*)smem;
    if (tid < 128) {
        int m = m0 + tid;
        s_tok[tid] = (m < cnt) ? g_tok[e * TT + m] : -1;
    }
    __syncthreads();

    const int wm = (wid & 3) * 32;
    const int wn = (wid >> 2) * 32;

    float accg[2][4][4], accu[2][4][4];
#pragma unroll
    for (int mf = 0; mf < 2; mf++)
#pragma unroll
        for (int nf = 0; nf < 4; nf++)
#pragma unroll
            for (int r = 0; r < 4; r++) { accg[mf][nf][r] = 0.f; accu[mf][nf][r] = 0.f; }

    g1_load(smem + 1024, s_tok, e, n0, 0, tid);
    CP_COMMIT();
    g1_load(smem + 1024 + STAGE_B, s_tok, e, n0, KC, tid);
    CP_COMMIT();

    const int NCH = HD / KC;   // 32
    for (int c = 0; c < NCH; c++) {
        CP_WAIT1();
        __syncthreads();   // stage c%3 ready; stage (c+2)%3 readers (iter c-1) all done

        char* sb = smem + 1024 + (c % NSTAGE) * STAGE_B;
        const uint32_t xs = smem_u32(sb);
        const uint32_t b1 = xs + 16384, b3 = xs + 24576;

#pragma unroll
        for (int kb = 0; kb < 4; kb++) {
            uint32_t af[2][4];
#pragma unroll
            for (int mf = 0; mf < 2; mf++)
                ldsm4(af[mf], xs + a_addr(wm + mf * 16, kb, lane));
            uint32_t r1[2][4], r3[2][4];
#pragma unroll
            for (int nf2 = 0; nf2 < 2; nf2++) {
                uint32_t ba = b_addr(wn + nf2 * 16, kb, lane);
                ldsm4(r1[nf2], b1 + ba);
                ldsm4(r3[nf2], b3 + ba);
            }
#pragma unroll
            for (int mf = 0; mf < 2; mf++)
#pragma unroll
                for (int nf = 0; nf < 4; nf++) {
                    const int h = nf >> 1, q = (nf & 1) * 2;
                    mma_f16(accg[mf][nf], af[mf], &r1[h][q]);
                    mma_f16(accu[mf][nf], af[mf], &r3[h][q]);
                }
            // mid-loop prefetch: issue next-next chunk's loads after the first
            // MMA batch so the HMMA pipe isn't starved at chunk entry, while
            // the loads still get ~3 kb-batches of latency cover
            if (kb == 0 && c + 2 < NCH)
                g1_load(smem + 1024 + ((c + 2) % NSTAGE) * STAGE_B, s_tok, e, n0, (c + 2) * KC, tid);
        }
        CP_COMMIT();
    }

    // epilogue: silu(g)*u -> fp16 act
#pragma unroll
    for (int mf = 0; mf < 2; mf++) {
#pragma unroll
        for (int rr = 0; rr < 2; rr++) {
            const int slot = m0 + wm + mf * 16 + rr * 8 + (lane >> 2);
            if (slot >= cnt) continue;
            const size_t base = (size_t)(e * TT + slot) * ID + n0;
#pragma unroll
            for (int nf = 0; nf < 4; nf++) {
                float g0 = accg[mf][nf][rr * 2 + 0], g1 = accg[mf][nf][rr * 2 + 1];
                float u0 = accu[mf][nf][rr * 2 + 0], u1 = accu[mf][nf][rr * 2 + 1];
                float a0 = u0 * g0 / (1.f + __expf(-g0));
                float a1 = u1 * g1 / (1.f + __expf(-g1));
                const int col = wn + nf * 8 + (lane & 3) * 2;
                *(__half2*)(g_act + base + col) = __floats2half2_rn(a0, a1);
            }
        }
    }
}

// ---------------- GEMM2: out[tok] += wt * (act[:,cb:ce] @ w2[:,cb:ce]^T) ----------------
// CTA 128(M) x 128(N); 8 warps 2x4 of 64x32. Grid: (n, m, nz) with n fastest.
__device__ __forceinline__ void g2_load(char* sb, int e, int m0, int cnt,
                                        int n0, int k0, int tid) {
    char* as = sb;
    char* ws = sb + 16384;
#pragma unroll
    for (int it = 0; it < 4; it++) {
        int i = tid + it * 256;
        int row = i >> 3, c16 = i & 7;
        uint32_t doff = SWZ((uint32_t)(row * 128 + c16 * 16));
        size_t aoff = (size_t)(e * TT + m0 + row) * ID + k0 + c16 * 8;
        cp16(smem_u32(as + doff), g_act + aoff, (m0 + row < cnt) ? 16 : 0);
        size_t woff = ((size_t)e * HD + n0 + row) * ID + k0 + c16 * 8;
        cp16(smem_u32(ws + doff), g_w2 + woff, 16);
    }
}

__global__ __launch_bounds__(256, 2)
void gemm2_kernel(int ebase, int cb, int ce, float* __restrict__ out) {
    extern __shared__ char smem[];
    const int e   = ebase + blockIdx.z;
    const int cnt = g_count[e];
    const int m0  = blockIdx.y * 128;
    if (m0 >= cnt) return;
    const int n0  = blockIdx.x * 128;
    const int tid  = threadIdx.x;
    const int wid  = tid >> 5, lane = tid & 31;

    int*   s_tok = (int*)smem;
    float* s_wt  = (float*)(smem + 512);
    if (tid < 128) {
        int m = m0 + tid;
        bool v = (m < cnt);
        s_tok[tid] = v ? g_tok[e * TT + m] : 0;
        s_wt[tid]  = v ? g_wt[e * TT + m] : 0.f;
    }
    __syncthreads();

    const int wm = (wid & 1) * 64;
    const int wn = (wid >> 1) * 32;

    float acc[4][4][4];
#pragma unroll
    for (int mf = 0; mf < 4; mf++)
#pragma unroll
        for (int nf = 0; nf < 4; nf++)
#pragma unroll
            for (int r = 0; r < 4; r++) acc[mf][nf][r] = 0.f;

    g2_load(smem + 1024 + (cb % NSTAGE) * STAGE_B, e, m0, cnt, n0, cb * KC, tid);
    CP_COMMIT();
    g2_load(smem + 1024 + ((cb + 1) % NSTAGE) * STAGE_B, e, m0, cnt, n0, (cb + 1) * KC, tid);
    CP_COMMIT();

    for (int c = cb; c < ce; c++) {
        CP_WAIT1();
        __syncthreads();

        char* sb = smem + 1024 + (c % NSTAGE) * STAGE_B;
        const uint32_t ab = smem_u32(sb);
        const uint32_t wb = ab + 16384;

#pragma unroll
        for (int kb = 0; kb < 4; kb++) {
            uint32_t af[4][4];
#pragma unroll
            for (int mf = 0; mf < 4; mf++)
                ldsm4(af[mf], ab + a_addr(wm + mf * 16, kb, lane));
            uint32_t rw[2][4];
#pragma unroll
            for (int nf2 = 0; nf2 < 2; nf2++)
                ldsm4(rw[nf2], wb + b_addr(wn + nf2 * 16, kb, lane));
#pragma unroll
            for (int mf = 0; mf < 4; mf++)
#pragma unroll
                for (int nf = 0; nf < 4; nf++) {
                    const int h = nf >> 1, q = (nf & 1) * 2;
                    mma_f16(acc[mf][nf], af[mf], &rw[h][q]);
                }
            // mid-loop prefetch (see gemm1)
            if (kb == 0 && c + 2 < ce)
                g2_load(smem + 1024 + ((c + 2) % NSTAGE) * STAGE_B, e, m0, cnt, n0, (c + 2) * KC, tid);
        }
        CP_COMMIT();
    }

    // epilogue: atomic weighted combine (partial over [cb, ce))
#pragma unroll
    for (int mf = 0; mf < 4; mf++) {
#pragma unroll
        for (int rr = 0; rr < 2; rr++) {
            const int lrow = wm + mf * 16 + rr * 8 + (lane >> 2);
            if (m0 + lrow >= cnt) continue;
            const int   tok = s_tok[lrow];
            const float wt  = s_wt[lrow];
            float* op = out + (size_t)tok * HD + n0;
#pragma unroll
            for (int nf = 0; nf < 4; nf++) {
                const int col = wn + nf * 8 + (lane & 3) * 2;
                atomicAdd(op + col,     wt * acc[mf][nf][rr * 2 + 0]);
                atomicAdd(op + col + 1, wt * acc[mf][nf][rr * 2 + 1]);
            }
        }
    }
}

#define NG1 5   // gemm1 launches: e0, e1, {2,3}, {4,5}, {6,7}

// ---------------- launch ----------------
extern "C" void kernel_launch(void* const* d_in, const int* in_sizes, int n_in,
                              void* d_out, int out_size) {
    const float* x  = (const float*)d_in[0];
    const float* gw = (const float*)d_in[1];
    const float* w1 = (const float*)d_in[2];
    const float* w3 = (const float*)d_in[3];
    const float* w2 = (const float*)d_in[4];
    float* out = (float*)d_out;

    static cudaStream_t s1 = nullptr, s2 = nullptr, s3 = nullptr;
    static cudaEvent_t ev_fork = nullptr, ev_w2 = nullptr, ev_rt = nullptr, ev_x = nullptr;
    static cudaEvent_t ev_ja = nullptr, ev_jb = nullptr, ev_jc = nullptr;
    static cudaEvent_t evw[NG1], ev1[NG1];
    static bool init_done = false;
    if (!init_done) {
        cudaFuncSetAttribute(gemm1_kernel, cudaFuncAttributeMaxDynamicSharedMemorySize, SMEM_SZ);
        cudaFuncSetAttribute(gemm2_kernel, cudaFuncAttributeMaxDynamicSharedMemorySize, SMEM_SZ);
        cudaStreamCreateWithFlags(&s1, cudaStreamNonBlocking);
        cudaStreamCreateWithFlags(&s2, cudaStreamNonBlocking);
        cudaStreamCreateWithFlags(&s3, cudaStreamNonBlocking);
        cudaEventCreateWithFlags(&ev_fork, cudaEventDisableTiming);
        cudaEventCreateWithFlags(&ev_w2,   cudaEventDisableTiming);
        cudaEventCreateWithFlags(&ev_rt,   cudaEventDisableTiming);
        cudaEventCreateWithFlags(&ev_x,    cudaEventDisableTiming);
        cudaEventCreateWithFlags(&ev_ja,   cudaEventDisableTiming);
        cudaEventCreateWithFlags(&ev_jb,   cudaEventDisableTiming);
        cudaEventCreateWithFlags(&ev_jc,   cudaEventDisableTiming);
        for (int p = 0; p < NG1; p++) {
            cudaEventCreateWithFlags(&evw[p], cudaEventDisableTiming);
            cudaEventCreateWithFlags(&ev1[p], cudaEventDisableTiming);
        }
        init_done = true;
    }

    void *cnt_a, *x_a, *w1_a, *w3_a, *w2_a;
    cudaGetSymbolAddress(&cnt_a, g_count);
    cudaGetSymbolAddress(&x_a,  g_x);
    cudaGetSymbolAddress(&w1_a, g_w1);
    cudaGetSymbolAddress(&w3_a, g_w3);
    cudaGetSymbolAddress(&w2_a, g_w2);

    cudaMemsetAsync(cnt_a, 0, sizeof(int) * NE, 0);
    cudaMemsetAsync(d_out, 0, sizeof(float) * (size_t)out_size, 0);

    const size_t ESZ = (size_t)ID * HD;          // elems per expert weight
    const int ne8 = (int)(ESZ / 8);
    const int nw8 = (int)(WSZ / 8);
    const int nx8 = TT * HD / 8;

    // cvt slice table: experts {0},{1},{2,3},{4,5},{6,7}
    const int cvt_e0[NG1] = {0, 1, 2, 4, 6};
    const int cvt_ne[NG1] = {1, 1, 2, 2, 2};

    // fork after memsets
    cudaEventRecord(ev_fork, 0);
    cudaStreamWaitEvent(s1, ev_fork, 0);
    cudaStreamWaitEvent(s2, ev_fork, 0);
    cudaStreamWaitEvent(s3, ev_fork, 0);

    // s2: cvt(x);  s3: route (independent of cvt(x) — reads fp32 x) in parallel
    cvt_kernel<<<(nx8 + 255) / 256, 256, 0, s2>>>(x, (__half*)x_a, nx8);
    cudaEventRecord(ev_x, s2);
    route_kernel<<<TT, 128, 0, s3>>>(x, gw);
    cudaEventRecord(ev_rt, s3);

    // s1: w1+w3 converts in slices {0},{1},{2,3},{4,5},{6,7}, then cvt(w2)
    for (int p = 0; p < NG1; p++) {
        const size_t off = (size_t)cvt_e0[p] * ESZ;
        const int    n8  = cvt_ne[p] * ne8;
        cvt2_kernel<<<(2 * n8 + 255) / 256, 256, 0, s1>>>(
            w1 + off, w3 + off,
            (__half*)w1_a + off, (__half*)w3_a + off, n8);
        cudaEventRecord(evw[p], s1);
    }
    cvt_kernel<<<(nw8 + 255) / 256, 256, 0, s1>>>(w2, (__half*)w2_a, nw8);
    cudaEventRecord(ev_w2, s1);

    // gemm1 launches: e0 (z=1), e1 (z=1), then pairs (z=2); alternate main/s2
    cudaStreamWaitEvent(0, ev_rt, 0);
    cudaStreamWaitEvent(0, ev_x, 0);
    cudaStreamWaitEvent(s2, ev_rt, 0);   // s2 has x by program order; needs route
    for (int p = 0; p < NG1; p++) {
        cudaStream_t gs = (p & 1) ? s2 : 0;
        cudaStreamWaitEvent(gs, evw[p], 0);
        dim3 g1(ID / 64, TT / 128, cvt_ne[p]);
        gemm1_kernel<<<g1, 256, SMEM_SZ, gs>>>(cvt_e0[p]);
        cudaEventRecord(ev1[p], gs);
    }

    // gemm2 quad0 (experts 0-3), full K, ALONE on s3
    dim3 g2(HD / 128, TT / 128, 4);
    cudaStreamWaitEvent(s3, ev_w2, 0);
    cudaStreamWaitEvent(s3, ev1[0], 0);
    cudaStreamWaitEvent(s3, ev1[1], 0);
    cudaStreamWaitEvent(s3, ev1[2], 0);
    gemm2_kernel<<<g2, 256, SMEM_SZ, s3>>>(0, 0, ID / KC, out);

    // gemm2 quad1 (experts 4-7), K-split halves on s1 and s2
    cudaStreamWaitEvent(s1, ev1[3], 0);  // s1 has w2 by program order
    cudaStreamWaitEvent(s1, ev1[4], 0);
    gemm2_kernel<<<g2, 256, SMEM_SZ, s1>>>(4, 0, ID / (2 * KC), out);
    cudaStreamWaitEvent(s2, ev_w2, 0);
    cudaStreamWaitEvent(s2, ev1[4], 0);  // ev1[3] implied by s2 stream order
    gemm2_kernel<<<g2, 256, SMEM_SZ, s2>>>(4, ID / (2 * KC), ID / KC, out);

    // join all three gemm2 streams back to main
    cudaEventRecord(ev_ja, s1);
    cudaEventRecord(ev_jb, s3);
    cudaEventRecord(ev_jc, s2);
    cudaStreamWaitEvent(0, ev_ja, 0);
    cudaStreamWaitEvent(0, ev_jb, 0);
    cudaStreamWaitEvent(0, ev_jc, 0);
}

// round 17
// speedup vs baseline: 1.0108x; 1.0108x over previous
#include <cuda_runtime.h>
#include <cuda_fp16.h>
#include <math.h>
#include <stdint.h>

// Problem constants
#define TT   2048      // tokens
#define HD   2048      // hidden
#define ID   5632      // intermediate
#define NE   8         // experts
#define KC   64        // K-chunk (fp16 elems) = 128B row

// ---------------- device scratch ----------------
__device__ int   g_count[NE];
__device__ int   g_tok[NE * TT];
__device__ float g_wt [NE * TT];

#define WSZ (NE * (size_t)ID * HD)
__device__ __half g_w1[WSZ];
__device__ __half g_w3[WSZ];
__device__ __half g_w2[WSZ];
__device__ __half g_x  [(size_t)TT * HD];
__device__ __half g_act[NE * (size_t)TT * ID];

// ---------------- helpers ----------------
__device__ __forceinline__ uint32_t smem_u32(const void* p) {
    return (uint32_t)__cvta_generic_to_shared(p);
}
#define SWZ(o) ((o) ^ (((o) >> 3) & 0x70))

__device__ __forceinline__ void cp16(uint32_t dst, const void* src, int sz) {
    asm volatile("cp.async.cg.shared.global [%0], [%1], 16, %2;"
                 :: "r"(dst), "l"(src), "r"(sz) : "memory");
}
#define CP_COMMIT() asm volatile("cp.async.commit_group;" ::: "memory")
#define CP_WAIT1()  asm volatile("cp.async.wait_group 1;" ::: "memory")

__device__ __forceinline__ void ldsm4(uint32_t* r, uint32_t addr) {
    asm volatile("ldmatrix.sync.aligned.m8n8.x4.shared.b16 {%0,%1,%2,%3}, [%4];"
                 : "=r"(r[0]), "=r"(r[1]), "=r"(r[2]), "=r"(r[3]) : "r"(addr));
}
__device__ __forceinline__ void mma_f16(float* d, const uint32_t* a, const uint32_t* b) {
    asm volatile("mma.sync.aligned.m16n8k16.row.col.f32.f16.f16.f32 "
                 "{%0,%1,%2,%3}, {%4,%5,%6,%7}, {%8,%9}, {%0,%1,%2,%3};"
                 : "+f"(d[0]), "+f"(d[1]), "+f"(d[2]), "+f"(d[3])
                 : "r"(a[0]), "r"(a[1]), "r"(a[2]), "r"(a[3]),
                   "r"(b[0]), "r"(b[1]));
}

// A-fragment ldmatrix address (m16 x k16 at (mbase, kb*16) within 128B-row tile)
__device__ __forceinline__ uint32_t a_addr(int mbase, int kb, int lane) {
    int row = mbase + ((lane >> 3) & 1) * 8 + (lane & 7);
    uint32_t off = (uint32_t)(row * 128 + kb * 32 + (lane >> 4) * 16);
    return SWZ(off);
}
// B-fragment ldmatrix address (n16 x k16 at (nbase, kb*16))
__device__ __forceinline__ uint32_t b_addr(int nbase, int kb, int lane) {
    int row = nbase + ((lane >> 4) << 3) + (lane & 7);
    uint32_t off = (uint32_t)(row * 128 + kb * 32 + ((lane >> 3) & 1) * 16);
    return SWZ(off);
}

// ---------------- fp32 -> fp16 convert (8 elems/thread) ----------------
__global__ void cvt_kernel(const float* __restrict__ src,
                           __half* __restrict__ dst, int n8) {
    int i = blockIdx.x * blockDim.x + threadIdx.x;
    if (i >= n8) return;
    const float4* s = (const float4*)src + (size_t)i * 2;
    float4 v0 = s[0];
    float4 v1 = s[1];
    __half2 p0 = __floats2half2_rn(v0.x, v0.y);
    __half2 p1 = __floats2half2_rn(v0.z, v0.w);
    __half2 p2 = __floats2half2_rn(v1.x, v1.y);
    __half2 p3 = __floats2half2_rn(v1.z, v1.w);
    uint4 u;
    u.x = *(uint32_t*)&p0; u.y = *(uint32_t*)&p1;
    u.z = *(uint32_t*)&p2; u.w = *(uint32_t*)&p3;
    ((uint4*)dst)[i] = u;
}

// fused w1+w3 convert over a contiguous slice
__global__ void cvt2_kernel(const float* __restrict__ sa,
                            const float* __restrict__ sb,
                            __half* __restrict__ da,
                            __half* __restrict__ db, int n8) {
    int i = blockIdx.x * blockDim.x + threadIdx.x;
    const float* src;
    __half* dst;
    if (i < n8) { src = sa; dst = da; }
    else        { src = sb; dst = db; i -= n8; if (i >= n8) return; }
    const float4* s = (const float4*)src + (size_t)i * 2;
    float4 v0 = s[0];
    float4 v1 = s[1];
    __half2 p0 = __floats2half2_rn(v0.x, v0.y);
    __half2 p1 = __floats2half2_rn(v0.z, v0.w);
    __half2 p2 = __floats2half2_rn(v1.x, v1.y);
    __half2 p3 = __floats2half2_rn(v1.z, v1.w);
    uint4 u;
    u.x = *(uint32_t*)&p0; u.y = *(uint32_t*)&p1;
    u.z = *(uint32_t*)&p2; u.w = *(uint32_t*)&p3;
    ((uint4*)dst)[i] = u;
}

// ---------------- router ----------------
__global__ void route_kernel(const float* __restrict__ x,
                             const float* __restrict__ gw) {
    const int t   = blockIdx.x;
    const int tid = threadIdx.x;   // 128
    float p[NE];
#pragma unroll
    for (int e = 0; e < NE; e++) p[e] = 0.f;
    const float* xr = x + (size_t)t * HD;
    for (int h = tid; h < HD; h += 128) {
        float xv = xr[h];
#pragma unroll
        for (int e = 0; e < NE; e++) p[e] += xv * gw[e * HD + h];
    }
    __shared__ float sh[NE][128];
#pragma unroll
    for (int e = 0; e < NE; e++) sh[e][tid] = p[e];
    __syncthreads();
    for (int off = 64; off > 0; off >>= 1) {
        if (tid < off) {
#pragma unroll
            for (int e = 0; e < NE; e++) sh[e][tid] += sh[e][tid + off];
        }
        __syncthreads();
    }
    if (tid == 0) {
        float l[NE];
#pragma unroll
        for (int e = 0; e < NE; e++) l[e] = sh[e][0];
        int i0 = 0;
#pragma unroll
        for (int e = 1; e < NE; e++) if (l[e] > l[i0]) i0 = e;
        int i1 = (i0 == 0) ? 1 : 0;
#pragma unroll
        for (int e = 0; e < NE; e++) if (e != i0 && l[e] > l[i1]) i1 = e;
        float d  = expf(l[i1] - l[i0]);
        float w0 = 1.f / (1.f + d);
        float w1 = d / (1.f + d);
        int p0 = atomicAdd(&g_count[i0], 1);
        g_tok[i0 * TT + p0] = t;  g_wt[i0 * TT + p0] = w0;
        int p1 = atomicAdd(&g_count[i1], 1);
        g_tok[i1 * TT + p1] = t;  g_wt[i1 * TT + p1] = w1;
    }
}

// SMEM: [0..512) s_tok, [512..1024) s_wt, 3 stages from 1024, 32KB each
#define STAGE_B 32768
#define NSTAGE  3
#define SMEM_SZ (1024 + NSTAGE * STAGE_B)

// ---------------- GEMM1: act = silu(x@w1^T) * (x@w3^T) ----------------
// CTA 128(M) x 64(N); 8 warps 4x2 of 32x32. Grid: (n, m, nz) with n fastest.
__device__ __forceinline__ void g1_load(char* sb, const int* s_tok,
                                        int e, int n0, int k0, int tid) {
    char* xs = sb;
    char* w1 = sb + 16384;
    char* w3 = sb + 24576;
#pragma unroll
    for (int it = 0; it < 4; it++) {
        int i = tid + it * 256;
        int row = i >> 3, c16 = i & 7;
        int tok = s_tok[row];
        uint32_t doff = SWZ((uint32_t)(row * 128 + c16 * 16));
        size_t goff = (size_t)(tok < 0 ? 0 : tok) * HD + k0 + c16 * 8;
        cp16(smem_u32(xs + doff), g_x + goff, (tok < 0) ? 0 : 16);
    }
#pragma unroll
    for (int it = 0; it < 2; it++) {
        int i = tid + it * 256;
        int row = i >> 3, c16 = i & 7;
        uint32_t doff = SWZ((uint32_t)(row * 128 + c16 * 16));
        size_t goff = ((size_t)e * ID + n0 + row) * HD + k0 + c16 * 8;
        cp16(smem_u32(w1 + doff), g_w1 + goff, 16);
        cp16(smem_u32(w3 + doff), g_w3 + goff, 16);
    }
}

__global__ __launch_bounds__(256, 2)
void gemm1_kernel(int ebase) {
    extern __shared__ char smem[];
    const int e   = ebase + blockIdx.z;
    const int cnt = g_count[e];
    const int m0  = blockIdx.y * 128;
    if (m0 >= cnt) return;
    const int n0  = blockIdx.x * 64;
    const int tid  = threadIdx.x;
    const int wid  = tid >> 5, lane = tid & 31;

    int* s_tok = (int*)smem;
    if (tid < 128) {
        int m = m0 + tid;
        s_tok[tid] = (m < cnt) ? g_tok[e * TT + m] : -1;
    }
    __syncthreads();

    const int wm = (wid & 3) * 32;
    const int wn = (wid >> 2) * 32;

    float accg[2][4][4], accu[2][4][4];
#pragma unroll
    for (int mf = 0; mf < 2; mf++)
#pragma unroll
        for (int nf = 0; nf < 4; nf++)
#pragma unroll
            for (int r = 0; r < 4; r++) { accg[mf][nf][r] = 0.f; accu[mf][nf][r] = 0.f; }

    g1_load(smem + 1024, s_tok, e, n0, 0, tid);
    CP_COMMIT();
    g1_load(smem + 1024 + STAGE_B, s_tok, e, n0, KC, tid);
    CP_COMMIT();

    const int NCH = HD / KC;   // 32
    for (int c = 0; c < NCH; c++) {
        CP_WAIT1();
        __syncthreads();   // stage c%3 ready; stage (c+2)%3 readers (iter c-1) all done

        char* sb = smem + 1024 + (c % NSTAGE) * STAGE_B;
        const uint32_t xs = smem_u32(sb);
        const uint32_t b1 = xs + 16384, b3 = xs + 24576;

#pragma unroll
        for (int kb = 0; kb < 4; kb++) {
            uint32_t af[2][4];
#pragma unroll
            for (int mf = 0; mf < 2; mf++)
                ldsm4(af[mf], xs + a_addr(wm + mf * 16, kb, lane));
            uint32_t r1[2][4], r3[2][4];
#pragma unroll
            for (int nf2 = 0; nf2 < 2; nf2++) {
                uint32_t ba = b_addr(wn + nf2 * 16, kb, lane);
                ldsm4(r1[nf2], b1 + ba);
                ldsm4(r3[nf2], b3 + ba);
            }
#pragma unroll
            for (int mf = 0; mf < 2; mf++)
#pragma unroll
                for (int nf = 0; nf < 4; nf++) {
                    const int h = nf >> 1, q = (nf & 1) * 2;
                    mma_f16(accg[mf][nf], af[mf], &r1[h][q]);
                    mma_f16(accu[mf][nf], af[mf], &r3[h][q]);
                }
        }
        if (c + 2 < NCH)
            g1_load(smem + 1024 + ((c + 2) % NSTAGE) * STAGE_B, s_tok, e, n0, (c + 2) * KC, tid);
        CP_COMMIT();
    }

    // epilogue: silu(g)*u -> fp16 act
#pragma unroll
    for (int mf = 0; mf < 2; mf++) {
#pragma unroll
        for (int rr = 0; rr < 2; rr++) {
            const int slot = m0 + wm + mf * 16 + rr * 8 + (lane >> 2);
            if (slot >= cnt) continue;
            const size_t base = (size_t)(e * TT + slot) * ID + n0;
#pragma unroll
            for (int nf = 0; nf < 4; nf++) {
                float g0 = accg[mf][nf][rr * 2 + 0], g1 = accg[mf][nf][rr * 2 + 1];
                float u0 = accu[mf][nf][rr * 2 + 0], u1 = accu[mf][nf][rr * 2 + 1];
                float a0 = u0 * g0 / (1.f + __expf(-g0));
                float a1 = u1 * g1 / (1.f + __expf(-g1));
                const int col = wn + nf * 8 + (lane & 3) * 2;
                *(__half2*)(g_act + base + col) = __floats2half2_rn(a0, a1);
            }
        }
    }
}

// ---------------- GEMM2: out[tok] += wt * (act[:,cb:ce] @ w2[:,cb:ce]^T) ----------------
// CTA 128(M) x 128(N); 8 warps 2x4 of 64x32. Grid: (n, m, nz) with n fastest.
__device__ __forceinline__ void g2_load(char* sb, int e, int m0, int cnt,
                                        int n0, int k0, int tid) {
    char* as = sb;
    char* ws = sb + 16384;
#pragma unroll
    for (int it = 0; it < 4; it++) {
        int i = tid + it * 256;
        int row = i >> 3, c16 = i & 7;
        uint32_t doff = SWZ((uint32_t)(row * 128 + c16 * 16));
        size_t aoff = (size_t)(e * TT + m0 + row) * ID + k0 + c16 * 8;
        cp16(smem_u32(as + doff), g_act + aoff, (m0 + row < cnt) ? 16 : 0);
        size_t woff = ((size_t)e * HD + n0 + row) * ID + k0 + c16 * 8;
        cp16(smem_u32(ws + doff), g_w2 + woff, 16);
    }
}

__global__ __launch_bounds__(256, 2)
void gemm2_kernel(int ebase, int cb, int ce, float* __restrict__ out) {
    extern __shared__ char smem[];
    const int e   = ebase + blockIdx.z;
    const int cnt = g_count[e];
    const int m0  = blockIdx.y * 128;
    if (m0 >= cnt) return;
    const int n0  = blockIdx.x * 128;
    const int tid  = threadIdx.x;
    const int wid  = tid >> 5, lane = tid & 31;

    int*   s_tok = (int*)smem;
    float* s_wt  = (float*)(smem + 512);
    if (tid < 128) {
        int m = m0 + tid;
        bool v = (m < cnt);
        s_tok[tid] = v ? g_tok[e * TT + m] : 0;
        s_wt[tid]  = v ? g_wt[e * TT + m] : 0.f;
    }
    __syncthreads();

    const int wm = (wid & 1) * 64;
    const int wn = (wid >> 1) * 32;

    float acc[4][4][4];
#pragma unroll
    for (int mf = 0; mf < 4; mf++)
#pragma unroll
        for (int nf = 0; nf < 4; nf++)
#pragma unroll
            for (int r = 0; r < 4; r++) acc[mf][nf][r] = 0.f;

    g2_load(smem + 1024 + (cb % NSTAGE) * STAGE_B, e, m0, cnt, n0, cb * KC, tid);
    CP_COMMIT();
    g2_load(smem + 1024 + ((cb + 1) % NSTAGE) * STAGE_B, e, m0, cnt, n0, (cb + 1) * KC, tid);
    CP_COMMIT();

    for (int c = cb; c < ce; c++) {
        CP_WAIT1();
        __syncthreads();

        char* sb = smem + 1024 + (c % NSTAGE) * STAGE_B;
        const uint32_t ab = smem_u32(sb);
        const uint32_t wb = ab + 16384;

#pragma unroll
        for (int kb = 0; kb < 4; kb++) {
            uint32_t af[4][4];
#pragma unroll
            for (int mf = 0; mf < 4; mf++)
                ldsm4(af[mf], ab + a_addr(wm + mf * 16, kb, lane));
            uint32_t rw[2][4];
#pragma unroll
            for (int nf2 = 0; nf2 < 2; nf2++)
                ldsm4(rw[nf2], wb + b_addr(wn + nf2 * 16, kb, lane));
#pragma unroll
            for (int mf = 0; mf < 4; mf++)
#pragma unroll
                for (int nf = 0; nf < 4; nf++) {
                    const int h = nf >> 1, q = (nf & 1) * 2;
                    mma_f16(acc[mf][nf], af[mf], &rw[h][q]);
                }
        }
        if (c + 2 < ce)
            g2_load(smem + 1024 + ((c + 2) % NSTAGE) * STAGE_B, e, m0, cnt, n0, (c + 2) * KC, tid);
        CP_COMMIT();
    }

    // epilogue: atomic weighted combine (partial over [cb, ce))
#pragma unroll
    for (int mf = 0; mf < 4; mf++) {
#pragma unroll
        for (int rr = 0; rr < 2; rr++) {
            const int lrow = wm + mf * 16 + rr * 8 + (lane >> 2);
            if (m0 + lrow >= cnt) continue;
            const int   tok = s_tok[lrow];
            const float wt  = s_wt[lrow];
            float* op = out + (size_t)tok * HD + n0;
#pragma unroll
            for (int nf = 0; nf < 4; nf++) {
                const int col = wn + nf * 8 + (lane & 3) * 2;
                atomicAdd(op + col,     wt * acc[mf][nf][rr * 2 + 0]);
                atomicAdd(op + col + 1, wt * acc[mf][nf][rr * 2 + 1]);
            }
        }
    }
}

#define NG1 5   // gemm1 launches: e0, e1, {2,3}, {4,5}, {6,7}

// ---------------- launch ----------------
extern "C" void kernel_launch(void* const* d_in, const int* in_sizes, int n_in,
                              void* d_out, int out_size) {
    const float* x  = (const float*)d_in[0];
    const float* gw = (const float*)d_in[1];
    const float* w1 = (const float*)d_in[2];
    const float* w3 = (const float*)d_in[3];
    const float* w2 = (const float*)d_in[4];
    float* out = (float*)d_out;

    static cudaStream_t s1 = nullptr, s2 = nullptr, s3 = nullptr;
    static cudaEvent_t ev_fork = nullptr, ev_w2 = nullptr, ev_rt = nullptr, ev_x = nullptr;
    static cudaEvent_t ev_ja = nullptr, ev_jb = nullptr, ev_jc = nullptr;
    static cudaEvent_t evw[NG1], ev1[NG1];
    static bool init_done = false;
    if (!init_done) {
        cudaFuncSetAttribute(gemm1_kernel, cudaFuncAttributeMaxDynamicSharedMemorySize, SMEM_SZ);
        cudaFuncSetAttribute(gemm2_kernel, cudaFuncAttributeMaxDynamicSharedMemorySize, SMEM_SZ);
        cudaStreamCreateWithFlags(&s1, cudaStreamNonBlocking);
        cudaStreamCreateWithFlags(&s2, cudaStreamNonBlocking);
        cudaStreamCreateWithFlags(&s3, cudaStreamNonBlocking);
        cudaEventCreateWithFlags(&ev_fork, cudaEventDisableTiming);
        cudaEventCreateWithFlags(&ev_w2,   cudaEventDisableTiming);
        cudaEventCreateWithFlags(&ev_rt,   cudaEventDisableTiming);
        cudaEventCreateWithFlags(&ev_x,    cudaEventDisableTiming);
        cudaEventCreateWithFlags(&ev_ja,   cudaEventDisableTiming);
        cudaEventCreateWithFlags(&ev_jb,   cudaEventDisableTiming);
        cudaEventCreateWithFlags(&ev_jc,   cudaEventDisableTiming);
        for (int p = 0; p < NG1; p++) {
            cudaEventCreateWithFlags(&evw[p], cudaEventDisableTiming);
            cudaEventCreateWithFlags(&ev1[p], cudaEventDisableTiming);
        }
        init_done = true;
    }

    void *cnt_a, *x_a, *w1_a, *w3_a, *w2_a;
    cudaGetSymbolAddress(&cnt_a, g_count);
    cudaGetSymbolAddress(&x_a,  g_x);
    cudaGetSymbolAddress(&w1_a, g_w1);
    cudaGetSymbolAddress(&w3_a, g_w3);
    cudaGetSymbolAddress(&w2_a, g_w2);

    cudaMemsetAsync(cnt_a, 0, sizeof(int) * NE, 0);
    cudaMemsetAsync(d_out, 0, sizeof(float) * (size_t)out_size, 0);

    const size_t ESZ = (size_t)ID * HD;          // elems per expert weight
    const int ne8 = (int)(ESZ / 8);
    const int nw8 = (int)(WSZ / 8);
    const int nx8 = TT * HD / 8;

    // cvt slice table: experts {0},{1},{2,3},{4,5},{6,7}
    const int cvt_e0[NG1] = {0, 1, 2, 4, 6};
    const int cvt_ne[NG1] = {1, 1, 2, 2, 2};

    // fork after memsets
    cudaEventRecord(ev_fork, 0);
    cudaStreamWaitEvent(s1, ev_fork, 0);
    cudaStreamWaitEvent(s2, ev_fork, 0);
    cudaStreamWaitEvent(s3, ev_fork, 0);

    // HEAD (only change vs R15): cvt(x) on s2 and route on s3 run in PARALLEL
    // (route reads fp32 x, independent of the fp16 convert)
    cvt_kernel<<<(nx8 + 255) / 256, 256, 0, s2>>>(x, (__half*)x_a, nx8);
    cudaEventRecord(ev_x, s2);
    route_kernel<<<TT, 128, 0, s3>>>(x, gw);
    cudaEventRecord(ev_rt, s3);

    // s1: w1+w3 converts in slices {0},{1},{2,3},{4,5},{6,7}, then cvt(w2)
    for (int p = 0; p < NG1; p++) {
        const size_t off = (size_t)cvt_e0[p] * ESZ;
        const int    n8  = cvt_ne[p] * ne8;
        cvt2_kernel<<<(2 * n8 + 255) / 256, 256, 0, s1>>>(
            w1 + off, w3 + off,
            (__half*)w1_a + off, (__half*)w3_a + off, n8);
        cudaEventRecord(evw[p], s1);
    }
    cvt_kernel<<<(nw8 + 255) / 256, 256, 0, s1>>>(w2, (__half*)w2_a, nw8);
    cudaEventRecord(ev_w2, s1);

    // gemm1 launches: e0 (z=1), e1 (z=1), then pairs (z=2); alternate main/s2
    cudaStreamWaitEvent(0, ev_rt, 0);
    cudaStreamWaitEvent(0, ev_x, 0);
    cudaStreamWaitEvent(s2, ev_rt, 0);   // s2 has x by program order; needs route
    for (int p = 0; p < NG1; p++) {
        cudaStream_t gs = (p & 1) ? s2 : 0;
        cudaStreamWaitEvent(gs, evw[p], 0);
        dim3 g1(ID / 64, TT / 128, cvt_ne[p]);
        gemm1_kernel<<<g1, 256, SMEM_SZ, gs>>>(cvt_e0[p]);
        cudaEventRecord(ev1[p], gs);
    }

    // gemm2 quad0 (experts 0-3), full K, ALONE on s3
    dim3 g2(HD / 128, TT / 128, 4);
    cudaStreamWaitEvent(s3, ev_w2, 0);
    cudaStreamWaitEvent(s3, ev1[0], 0);
    cudaStreamWaitEvent(s3, ev1[1], 0);
    cudaStreamWaitEvent(s3, ev1[2], 0);
    gemm2_kernel<<<g2, 256, SMEM_SZ, s3>>>(0, 0, ID / KC, out);

    // gemm2 quad1 (experts 4-7), K-split halves on s1 and s2
    cudaStreamWaitEvent(s1, ev1[3], 0);  // s1 has w2 by program order
    cudaStreamWaitEvent(s1, ev1[4], 0);
    gemm2_kernel<<<g2, 256, SMEM_SZ, s1>>>(4, 0, ID / (2 * KC), out);
    cudaStreamWaitEvent(s2, ev_w2, 0);
    cudaStreamWaitEvent(s2, ev1[4], 0);  // ev1[3] implied by s2 stream order
    gemm2_kernel<<<g2, 256, SMEM_SZ, s2>>>(4, ID / (2 * KC), ID / KC, out);

    // join all three gemm2 streams back to main
    cudaEventRecord(ev_ja, s1);
    cudaEventRecord(ev_jb, s3);
    cudaEventRecord(ev_jc, s2);
    cudaStreamWaitEvent(0, ev_ja, 0);
    cudaStreamWaitEvent(0, ev_jb, 0);
    cudaStreamWaitEvent(0, ev_jc, 0);
}